// round 15
// baseline (speedup 1.0000x reference)
#include <cuda_runtime.h>
#include <cuda_fp16.h>
#include <cstdint>

// Problem constants
#define BB   4
#define TT   512
#define KK   63
#define DD   384
#define DFF  1536
#define MM   (BB*TT)          // 2048
#define NOUT 96
#define FREQ 1016

// ---------------------------------------------------------------------------
// Scratch (device globals; ONLY referenced from device code — see R3 bug).
// ---------------------------------------------------------------------------
__device__ __align__(16) __half g_An [(size_t)KK * MM * DD];
__device__ __align__(16) __half g_W0T[(size_t)KK * DFF * DD];
__device__ __align__(16) __half g_W1T[(size_t)KK * NOUT * DFF];
__device__ __align__(16) __half g_H1 [(size_t)KK * MM * DFF];

// ---------------------------------------------------------------------------
// Portable PTX helpers (plain sm_103)
// ---------------------------------------------------------------------------
__device__ __forceinline__ uint32_t smem_u32(const void* p) {
    uint32_t a;
    asm("{ .reg .u64 t; cvta.to.shared.u64 t, %1; cvt.u32.u64 %0, t; }"
        : "=r"(a) : "l"(p));
    return a;
}
#define CP16(dst, src) \
    asm volatile("cp.async.cg.shared.global [%0], [%1], 16;" \
                 :: "r"(dst), "l"(src) : "memory")
#define CP_COMMIT() asm volatile("cp.async.commit_group;" ::: "memory")
#define CP_WAITN(n) asm volatile("cp.async.wait_group %0;" :: "n"(n) : "memory")

__device__ __forceinline__ void ldsm4(uint32_t r[4], uint32_t addr) {
    asm volatile("ldmatrix.sync.aligned.m8n8.x4.shared.b16 {%0,%1,%2,%3}, [%4];"
        : "=r"(r[0]), "=r"(r[1]), "=r"(r[2]), "=r"(r[3]) : "r"(addr));
}
// fp32-accumulate (gemm2, numerically safe)
__device__ __forceinline__ void mma_f16(float c[4], const uint32_t a[4],
                                        uint32_t b0, uint32_t b1) {
    asm volatile(
        "mma.sync.aligned.m16n8k16.row.col.f32.f16.f16.f32 "
        "{%0,%1,%2,%3}, {%4,%5,%6,%7}, {%8,%9}, {%0,%1,%2,%3};"
        : "+f"(c[0]), "+f"(c[1]), "+f"(c[2]), "+f"(c[3])
        : "r"(a[0]), "r"(a[1]), "r"(a[2]), "r"(a[3]), "r"(b0), "r"(b1));
}
// fp16-accumulate (gemm1 probe): D,C are 2 regs of half2
__device__ __forceinline__ void mma_f16a(uint32_t d[2], const uint32_t a[4],
                                         uint32_t b0, uint32_t b1) {
    asm volatile(
        "mma.sync.aligned.m16n8k16.row.col.f16.f16.f16.f16 "
        "{%0,%1}, {%2,%3,%4,%5}, {%6,%7}, {%0,%1};"
        : "+r"(d[0]), "+r"(d[1])
        : "r"(a[0]), "r"(a[1]), "r"(a[2]), "r"(a[3]), "r"(b0), "r"(b1));
}

// Swizzled byte offset in a [rows x 32 halves] tile packed as 128B lines
// (2 rows/line). Property: tswz(r,c) == tswz(r,0) ^ (c<<4).
__device__ __forceinline__ uint32_t tswz(int r, int c) {
    uint32_t line = (uint32_t)r >> 1;
    uint32_t pos  = ((((uint32_t)r & 1u) << 2) | (uint32_t)c) ^ (line & 7u);
    return line * 128u + pos * 16u;
}

// ---------------------------------------------------------------------------
// RMSNorm + gamma -> fp16.  x[m][k][d] -> An[k][m][d]
// ---------------------------------------------------------------------------
__global__ __launch_bounds__(256) void rms_kernel(
    const float* __restrict__ x, const float* __restrict__ gamma)
{
    int gt = blockIdx.x * blockDim.x + threadIdx.x;
    int row = gt >> 5, lane = gt & 31;
    if (row >= MM * KK) return;
    int m = row / KK, k = row - m * KK;

    const float* xr = x + (size_t)row * DD;
    float4 v[3];
    float s = 0.f;
    #pragma unroll
    for (int i = 0; i < 3; i++) {
        v[i] = *reinterpret_cast<const float4*>(&xr[(lane + i * 32) * 4]);
        s += v[i].x*v[i].x + v[i].y*v[i].y + v[i].z*v[i].z + v[i].w*v[i].w;
    }
    #pragma unroll
    for (int o = 16; o > 0; o >>= 1) s += __shfl_xor_sync(0xffffffffu, s, o);
    s = rsqrtf(s * (1.0f / DD) + 1e-8f);

    const float* gk = gamma + k * DD;
    __half* oh = g_An + ((size_t)k * MM + m) * DD;
    #pragma unroll
    for (int i = 0; i < 3; i++) {
        int d = (lane + i * 32) * 4;
        float4 g = *reinterpret_cast<const float4*>(&gk[d]);
        __half2 h0 = __floats2half2_rn(v[i].x*s*g.x, v[i].y*s*g.y);
        __half2 h1 = __floats2half2_rn(v[i].z*s*g.z, v[i].w*s*g.w);
        uint2 H;
        H.x = *reinterpret_cast<uint32_t*>(&h0);
        H.y = *reinterpret_cast<uint32_t*>(&h1);
        *reinterpret_cast<uint2*>(oh + d) = H;
    }
}

// ---------------------------------------------------------------------------
// Per-band transpose + fp16 round. in[k][R][C] -> dst[k][C][R]
// ---------------------------------------------------------------------------
template <int SEL>
__global__ __launch_bounds__(256) void transpose_h_kernel(
    const float* __restrict__ in, int R, int C)
{
    __half* __restrict__ oh = (SEL == 0) ? g_W0T : g_W1T;

    __shared__ float tile[32][33];
    const float* inp = in + (size_t)blockIdx.z * R * C;
    size_t obase = (size_t)blockIdx.z * C * R;
    int r0 = blockIdx.y * 32, c0 = blockIdx.x * 32;
    int tx = threadIdx.x, ty = threadIdx.y;

    #pragma unroll
    for (int j = 0; j < 2; j++) {
        int r = ty + 16 * j;
        float2 v = *reinterpret_cast<const float2*>(
            &inp[(size_t)(r0 + r) * C + c0 + tx * 2]);
        tile[r][tx * 2 + 0] = v.x;
        tile[r][tx * 2 + 1] = v.y;
    }
    __syncthreads();
    {
        int lin = ty * 16 + tx;
        int orow = lin >> 3;
        int oseg = lin & 7;
        int oc = c0 + orow;
        __half2 p0 = __floats2half2_rn(tile[oseg*4+0][orow], tile[oseg*4+1][orow]);
        __half2 p1 = __floats2half2_rn(tile[oseg*4+2][orow], tile[oseg*4+3][orow]);
        uint2 H;
        H.x = *reinterpret_cast<uint32_t*>(&p0);
        H.y = *reinterpret_cast<uint32_t*>(&p1);
        *reinterpret_cast<uint2*>(&oh[obase + (size_t)oc * R + r0 + oseg * 4]) = H;
    }
}

// ---------------------------------------------------------------------------
// GEMM1 (mma.sync, FP16-ACCUM PROBE): H1[k] = tanh(An @ W0T^T + b0)
//   Block 128x64, K-step 32 (12 iters), 4-stage cp.async, ONE sync/iter.
//   8 warps as 4(M)x2(N): warp tile 32x32. fp16 D chained over K=64 windows
//   (2 iters), flushed into fp32 master accumulators. ~105 regs, 2 CTAs/SM.
//   Stage: A 8K | B 4K = 12KB x4 = 48KB.
// ---------------------------------------------------------------------------
#define G1_STAGE 12288
#define G1_SMEM  (4*G1_STAGE)

__global__ __launch_bounds__(256, 2) void gemm1_mma(const float* __restrict__ b0)
{
    extern __shared__ char smem[];
    const uint32_t sb = smem_u32(smem);
    const int t = threadIdx.x, wid = t >> 5, lane = t & 31;
    const int k = blockIdx.z, mb = blockIdx.y * 128, nb = blockIdx.x * 64;
    const int wm = wid & 3, wn = wid >> 2;

    const __half* gA = g_An  + ((size_t)k * MM  + mb) * DD;
    const __half* gB = g_W0T + ((size_t)k * DFF + nb) * DD;

    // 3 cp chunks/thread: ids 0..511 A (128r x 4c16), 512..767 B (64r x 4c16)
    const __half* gbase[3];
    uint32_t sdst[3];
    #pragma unroll
    for (int j = 0; j < 3; j++) {
        int id = t + j * 256;
        int c = id & 3;
        if (id < 512) { int r = id >> 2;
                        gbase[j] = gA + (size_t)r * DD + c * 8;
                        sdst[j]  = tswz(r, c); }
        else          { int r = (id - 512) >> 2;
                        gbase[j] = gB + (size_t)r * DD + c * 8;
                        sdst[j]  = 8192u + tswz(r, c); }
    }

    const uint32_t laneXor = (uint32_t)((lane >> 4) << 4);
    uint32_t aO[2], bO[2];
    #pragma unroll
    for (int mf = 0; mf < 2; mf++)
        aO[mf] = tswz(wm * 32 + mf * 16 + (lane & 15), 0) ^ laneXor;
    #pragma unroll
    for (int g = 0; g < 2; g++)
        bO[g] = (tswz(wn * 32 + g * 16 + (lane & 15), 0) ^ laneXor) + 8192u;

    float acc[2][4][4];          // fp32 master
    #pragma unroll
    for (int a = 0; a < 2; a++)
        #pragma unroll
        for (int b = 0; b < 4; b++)
            #pragma unroll
            for (int c = 0; c < 4; c++) acc[a][b][c] = 0.f;

    uint32_t dch[2][4][2];       // fp16 chain (K=64 window)
    #pragma unroll
    for (int a = 0; a < 2; a++)
        #pragma unroll
        for (int b = 0; b < 4; b++) { dch[a][b][0] = 0u; dch[a][b][1] = 0u; }

    #pragma unroll
    for (int st = 0; st < 3; st++) {
        #pragma unroll
        for (int j = 0; j < 3; j++)
            CP16(sb + st * G1_STAGE + sdst[j], gbase[j] + st * 32);
        CP_COMMIT();
    }

    #pragma unroll 1
    for (int it4 = 0; it4 < 3; ++it4) {
        #pragma unroll
        for (int ph = 0; ph < 4; ph++) {
            const int it = it4 * 4 + ph;
            const uint32_t stb = sb + (uint32_t)(ph * G1_STAGE);
            if (it < 10) CP_WAITN(2);
            else if (it == 10) CP_WAITN(1);
            else CP_WAITN(0);
            __syncthreads();
            if (it + 3 < 12) {
                const uint32_t stn = sb + (uint32_t)(((ph + 3) & 3) * G1_STAGE);
                const int k0 = (it + 3) * 32;
                #pragma unroll
                for (int j = 0; j < 3; j++) CP16(stn + sdst[j], gbase[j] + k0);
                CP_COMMIT();
            }

            #pragma unroll
            for (int kc = 0; kc < 2; kc++) {
                const uint32_t kx = (uint32_t)(kc << 5);
                uint32_t a[2][4], b[2][4];
                #pragma unroll
                for (int g = 0; g < 2; g++) ldsm4(b[g], stb + (bO[g] ^ kx));
                #pragma unroll
                for (int mf = 0; mf < 2; mf++) ldsm4(a[mf], stb + (aO[mf] ^ kx));
                #pragma unroll
                for (int mf = 0; mf < 2; mf++)
                    #pragma unroll
                    for (int nf = 0; nf < 4; nf++) {
                        int g = nf >> 1, s = nf & 1;
                        mma_f16a(dch[mf][nf], a[mf], b[g][s], b[g][s + 2]);
                    }
            }

            // flush fp16 window -> fp32 master every 2 iters (K=64)
            if (it & 1) {
                #pragma unroll
                for (int mf = 0; mf < 2; mf++)
                    #pragma unroll
                    for (int nf = 0; nf < 4; nf++) {
                        float2 f0 = __half22float2(
                            *reinterpret_cast<__half2*>(&dch[mf][nf][0]));
                        float2 f1 = __half22float2(
                            *reinterpret_cast<__half2*>(&dch[mf][nf][1]));
                        acc[mf][nf][0] += f0.x;
                        acc[mf][nf][1] += f0.y;
                        acc[mf][nf][2] += f1.x;
                        acc[mf][nf][3] += f1.y;
                        dch[mf][nf][0] = 0u;
                        dch[mf][nf][1] = 0u;
                    }
            }
        }
    }

    // epilogue: bias + tanh -> g_H1 (fp16)
    #pragma unroll
    for (int nf = 0; nf < 4; nf++) {
        int n = nb + wn * 32 + nf * 8 + 2 * (lane & 3);
        float2 bias = *reinterpret_cast<const float2*>(&b0[k * DFF + n]);
        #pragma unroll
        for (int mf = 0; mf < 2; mf++) {
            #pragma unroll
            for (int h = 0; h < 2; h++) {
                int m = mb + wm * 32 + mf * 16 + (lane >> 2) + h * 8;
                float v0 = tanhf(acc[mf][nf][h * 2 + 0] + bias.x);
                float v1 = tanhf(acc[mf][nf][h * 2 + 1] + bias.y);
                __half2 hv = __floats2half2_rn(v0, v1);
                size_t off = ((size_t)k * MM + m) * DFF + n;
                *reinterpret_cast<uint32_t*>(g_H1 + off) =
                    *reinterpret_cast<uint32_t*>(&hv);
            }
        }
    }
}

// ---------------------------------------------------------------------------
// GEMM2 (mma.sync f16, fp32 accum): C = H1 @ W1T^T + b1; GLU; scatter-add.
//   Block 128x96, K-step 32 (48 iters), 4-stage cp.async, ONE sync/iter.
//   8 warps as 4(M)x2(N): warp tile 32x48. 2 CTAs/SM. (R12 config.)
// ---------------------------------------------------------------------------
#define G2_STAGE 14336
#define G2_SMEM  (4*G2_STAGE)

__global__ __launch_bounds__(256, 2) void gemm2_mma(
    const float* __restrict__ b1, float* __restrict__ out)
{
    extern __shared__ char smem[];
    const uint32_t sb = smem_u32(smem);
    const int t = threadIdx.x, wid = t >> 5, lane = t & 31;
    const int k = blockIdx.y, mb = blockIdx.x * 128;
    const int wm = wid & 3, wn = wid >> 2;

    const __half* gA = g_H1  + ((size_t)k * MM + mb) * DFF;
    const __half* gB = g_W1T + (size_t)k * NOUT * DFF;

    const __half* gbase[4];
    uint32_t sdst[4];
    #pragma unroll
    for (int j = 0; j < 4; j++) {
        int id = t + j * 256;
        if (id >= 896) { gbase[j] = nullptr; sdst[j] = 0; continue; }
        int c = id & 3;
        if (id < 512) { int r = id >> 2;
                        gbase[j] = gA + (size_t)r * DFF + c * 8;
                        sdst[j]  = tswz(r, c); }
        else          { int r = (id - 512) >> 2;
                        gbase[j] = gB + (size_t)r * DFF + c * 8;
                        sdst[j]  = 8192u + tswz(r, c); }
    }

    const uint32_t laneXor = (uint32_t)((lane >> 4) << 4);
    uint32_t aO[2], bO[3];
    #pragma unroll
    for (int mf = 0; mf < 2; mf++)
        aO[mf] = tswz(wm * 32 + mf * 16 + (lane & 15), 0) ^ laneXor;
    #pragma unroll
    for (int g = 0; g < 3; g++)
        bO[g] = (tswz(wn * 48 + g * 16 + (lane & 15), 0) ^ laneXor) + 8192u;

    float acc[2][6][4];
    #pragma unroll
    for (int a = 0; a < 2; a++)
        #pragma unroll
        for (int b = 0; b < 6; b++)
            #pragma unroll
            for (int c = 0; c < 4; c++) acc[a][b][c] = 0.f;

    #pragma unroll
    for (int st = 0; st < 3; st++) {
        #pragma unroll
        for (int j = 0; j < 4; j++)
            if (gbase[j]) CP16(sb + st * G2_STAGE + sdst[j], gbase[j] + st * 32);
        CP_COMMIT();
    }

    #pragma unroll 1
    for (int it4 = 0; it4 < 12; ++it4) {
        #pragma unroll
        for (int ph = 0; ph < 4; ph++) {
            const int it = it4 * 4 + ph;
            const uint32_t stb = sb + (uint32_t)(ph * G2_STAGE);
            if (it < 46) CP_WAITN(2);
            else if (it == 46) CP_WAITN(1);
            else CP_WAITN(0);
            __syncthreads();
            if (it + 3 < 48) {
                const uint32_t stn = sb + (uint32_t)(((ph + 3) & 3) * G2_STAGE);
                const int k0 = (it + 3) * 32;
                #pragma unroll
                for (int j = 0; j < 4; j++)
                    if (gbase[j]) CP16(stn + sdst[j], gbase[j] + k0);
                CP_COMMIT();
            }

            #pragma unroll
            for (int kc = 0; kc < 2; kc++) {
                const uint32_t kx = (uint32_t)(kc << 5);
                uint32_t a[2][4], b[3][4];
                #pragma unroll
                for (int g = 0; g < 3; g++) ldsm4(b[g], stb + (bO[g] ^ kx));
                #pragma unroll
                for (int mf = 0; mf < 2; mf++) ldsm4(a[mf], stb + (aO[mf] ^ kx));
                #pragma unroll
                for (int mf = 0; mf < 2; mf++)
                    #pragma unroll
                    for (int nf = 0; nf < 6; nf++) {
                        int g = nf >> 1, s = nf & 1;
                        mma_f16(acc[mf][nf], a[mf], b[g][s], b[g][s + 2]);
                    }
            }
        }
    }
    __syncthreads();

    // epilogue: stage C in smem, then GLU + scatter-add
    float* Cs = reinterpret_cast<float*>(smem);   // 128 x 100 floats
    #pragma unroll
    for (int nf = 0; nf < 6; nf++) {
        int n = wn * 48 + nf * 8 + 2 * (lane & 3);
        #pragma unroll
        for (int mf = 0; mf < 2; mf++) {
            #pragma unroll
            for (int h = 0; h < 2; h++) {
                int m = wm * 32 + mf * 16 + (lane >> 2) + h * 8;
                float2 v;
                v.x = acc[mf][nf][h * 2 + 0];
                v.y = acc[mf][nf][h * 2 + 1];
                *reinterpret_cast<float2*>(&Cs[m * 100 + n]) = v;
            }
        }
    }
    __syncthreads();

    {
        int m = t >> 1;
        int j0 = (t & 1) * 24;
        int gm = mb + m, bidx = gm >> 9, tidx = gm & 511;
        const float* bA = b1 + k * NOUT;
        #pragma unroll
        for (int jj = 0; jj < 24; jj++) {
            int j = j0 + jj;
            float a = Cs[m * 100 + j]      + bA[j];
            float g = Cs[m * 100 + j + 48] + bA[j + 48];
            float ch = a * (1.0f / (1.0f + __expf(-g)));
            int p = k * 32 + j;
            int oi = ((bidx * 2 + (p & 1)) * TT + tidx) * FREQ + (p >> 1);
            atomicAdd(&out[oi], ch);
        }
    }
}

// ---------------------------------------------------------------------------
extern "C" void kernel_launch(void* const* d_in, const int* in_sizes, int n_in,
                              void* d_out, int out_size)
{
    (void)in_sizes; (void)n_in;
    const float* x     = (const float*)d_in[0];
    const float* gamma = (const float*)d_in[1];
    const float* W0    = (const float*)d_in[2];
    const float* b0    = (const float*)d_in[3];
    const float* W1    = (const float*)d_in[4];
    const float* b1    = (const float*)d_in[5];
    float*       out   = (float*)d_out;

    cudaFuncSetAttribute(gemm1_mma, cudaFuncAttributeMaxDynamicSharedMemorySize, G1_SMEM);
    cudaFuncSetAttribute(gemm2_mma, cudaFuncAttributeMaxDynamicSharedMemorySize, G2_SMEM);

    cudaMemsetAsync(out, 0, (size_t)out_size * sizeof(float));

    {
        dim3 b(16, 16);
        dim3 g0(DFF / 32, DD / 32, KK);
        transpose_h_kernel<0><<<g0, b>>>(W0, DD, DFF);
        dim3 g1(NOUT / 32, DFF / 32, KK);
        transpose_h_kernel<1><<<g1, b>>>(W1, DFF, NOUT);
    }

    rms_kernel<<<(MM * KK * 32 + 255) / 256, 256>>>(x, gamma);

    dim3 g1(DFF / 64, MM / 128, KK);       // (24, 16, 63)
    gemm1_mma<<<g1, 256, G1_SMEM>>>(b0);

    dim3 g2(MM / 128, KK);                 // (16, 63)
    gemm2_mma<<<g2, 256, G2_SMEM>>>(b1, out);
}

// round 16
// speedup vs baseline: 1.1829x; 1.1829x over previous
#include <cuda_runtime.h>
#include <cuda_fp16.h>
#include <cstdint>

// Problem constants
#define BB   4
#define TT   512
#define KK   63
#define DD   384
#define DFF  1536
#define MM   (BB*TT)          // 2048
#define NOUT 96
#define FREQ 1016

// Fused-pre block ranges
#define NB_W0   (48*12*KK)    // W0 transpose: (DFF/32)*(DD/32)*KK = 36288
#define NB_W1   (3*48*KK)     // W1 transpose: (NOUT/32)*(DFF/32)*KK = 9072
#define NB_RMS  ((MM*KK*32 + 255)/256)  // 16128
#define NB_ZERO 1017          // zero out: 4,161,536 floats / 4096 per block

// ---------------------------------------------------------------------------
// Scratch (device globals; ONLY referenced from device code — see R3 bug).
// ---------------------------------------------------------------------------
__device__ __align__(16) __half g_An [(size_t)KK * MM * DD];
__device__ __align__(16) __half g_W0T[(size_t)KK * DFF * DD];
__device__ __align__(16) __half g_W1T[(size_t)KK * NOUT * DFF];
__device__ __align__(16) __half g_H1 [(size_t)KK * MM * DFF];

// ---------------------------------------------------------------------------
// Portable PTX helpers (plain sm_103)
// ---------------------------------------------------------------------------
__device__ __forceinline__ uint32_t smem_u32(const void* p) {
    uint32_t a;
    asm("{ .reg .u64 t; cvta.to.shared.u64 t, %1; cvt.u32.u64 %0, t; }"
        : "=r"(a) : "l"(p));
    return a;
}
#define CP16(dst, src) \
    asm volatile("cp.async.cg.shared.global [%0], [%1], 16;" \
                 :: "r"(dst), "l"(src) : "memory")
#define CP_COMMIT() asm volatile("cp.async.commit_group;" ::: "memory")
#define CP_WAITN(n) asm volatile("cp.async.wait_group %0;" :: "n"(n) : "memory")

__device__ __forceinline__ void ldsm4(uint32_t r[4], uint32_t addr) {
    asm volatile("ldmatrix.sync.aligned.m8n8.x4.shared.b16 {%0,%1,%2,%3}, [%4];"
        : "=r"(r[0]), "=r"(r[1]), "=r"(r[2]), "=r"(r[3]) : "r"(addr));
}
__device__ __forceinline__ void mma_f16(float c[4], const uint32_t a[4],
                                        uint32_t b0, uint32_t b1) {
    asm volatile(
        "mma.sync.aligned.m16n8k16.row.col.f32.f16.f16.f32 "
        "{%0,%1,%2,%3}, {%4,%5,%6,%7}, {%8,%9}, {%0,%1,%2,%3};"
        : "+f"(c[0]), "+f"(c[1]), "+f"(c[2]), "+f"(c[3])
        : "r"(a[0]), "r"(a[1]), "r"(a[2]), "r"(a[3]), "r"(b0), "r"(b1));
}

// Swizzled byte offset in a [rows x 32 halves] tile packed as 128B lines
// (2 rows/line). Property: tswz(r,c) == tswz(r,0) ^ (c<<4).
__device__ __forceinline__ uint32_t tswz(int r, int c) {
    uint32_t line = (uint32_t)r >> 1;
    uint32_t pos  = ((((uint32_t)r & 1u) << 2) | (uint32_t)c) ^ (line & 7u);
    return line * 128u + pos * 16u;
}

// ---------------------------------------------------------------------------
// Fused preprocessing: one launch, block-range dispatch of 4 independent jobs:
//  [0, NB_W0)                      : W0 transpose+fp16  [k][384][1536]->[k][1536][384]
//  [NB_W0, +NB_W1)                 : W1 transpose+fp16  [k][1536][96] ->[k][96][1536]
//  [.., +NB_RMS)                   : RMSNorm+gamma -> g_An (fp16)
//  [.., +NB_ZERO)                  : zero the output buffer
// ---------------------------------------------------------------------------
__device__ __forceinline__ void transpose_body(
    const float* __restrict__ in, __half* __restrict__ oh,
    int R, int C, int bx, int by, int bz, int t)
{
    __shared__ float tile[32][33];
    const float* inp = in + (size_t)bz * R * C;
    size_t obase = (size_t)bz * C * R;
    int r0 = by * 32, c0 = bx * 32;
    int tx = t & 15, ty = t >> 4;

    #pragma unroll
    for (int j = 0; j < 2; j++) {
        int r = ty + 16 * j;
        float2 v = *reinterpret_cast<const float2*>(
            &inp[(size_t)(r0 + r) * C + c0 + tx * 2]);
        tile[r][tx * 2 + 0] = v.x;
        tile[r][tx * 2 + 1] = v.y;
    }
    __syncthreads();
    {
        int orow = t >> 3;
        int oseg = t & 7;
        int oc = c0 + orow;
        __half2 p0 = __floats2half2_rn(tile[oseg*4+0][orow], tile[oseg*4+1][orow]);
        __half2 p1 = __floats2half2_rn(tile[oseg*4+2][orow], tile[oseg*4+3][orow]);
        uint2 H;
        H.x = *reinterpret_cast<uint32_t*>(&p0);
        H.y = *reinterpret_cast<uint32_t*>(&p1);
        *reinterpret_cast<uint2*>(&oh[obase + (size_t)oc * R + r0 + oseg * 4]) = H;
    }
}

__global__ __launch_bounds__(256) void pre_fused(
    const float* __restrict__ x, const float* __restrict__ gamma,
    const float* __restrict__ W0, const float* __restrict__ W1,
    float* __restrict__ out, int out_size)
{
    const int t = threadIdx.x;
    int id = blockIdx.x;

    if (id < NB_W0) {
        int bz = id / (48 * 12);
        int rem = id - bz * (48 * 12);
        int by = rem / 48, bx = rem - by * 48;
        transpose_body(W0, g_W0T, DD, DFF, bx, by, bz, t);
        return;
    }
    id -= NB_W0;
    if (id < NB_W1) {
        int bz = id / (3 * 48);
        int rem = id - bz * (3 * 48);
        int by = rem / 3, bx = rem - by * 3;
        transpose_body(W1, g_W1T, DFF, NOUT, bx, by, bz, t);
        return;
    }
    id -= NB_W1;
    if (id < NB_RMS) {
        int gt = id * 256 + t;
        int row = gt >> 5, lane = gt & 31;
        if (row >= MM * KK) return;
        int m = row / KK, k = row - m * KK;

        const float* xr = x + (size_t)row * DD;
        float4 v[3];
        float s = 0.f;
        #pragma unroll
        for (int i = 0; i < 3; i++) {
            v[i] = *reinterpret_cast<const float4*>(&xr[(lane + i * 32) * 4]);
            s += v[i].x*v[i].x + v[i].y*v[i].y + v[i].z*v[i].z + v[i].w*v[i].w;
        }
        #pragma unroll
        for (int o = 16; o > 0; o >>= 1) s += __shfl_xor_sync(0xffffffffu, s, o);
        s = rsqrtf(s * (1.0f / DD) + 1e-8f);

        const float* gk = gamma + k * DD;
        __half* oh = g_An + ((size_t)k * MM + m) * DD;
        #pragma unroll
        for (int i = 0; i < 3; i++) {
            int d = (lane + i * 32) * 4;
            float4 g = *reinterpret_cast<const float4*>(&gk[d]);
            __half2 h0 = __floats2half2_rn(v[i].x*s*g.x, v[i].y*s*g.y);
            __half2 h1 = __floats2half2_rn(v[i].z*s*g.z, v[i].w*s*g.w);
            uint2 H;
            H.x = *reinterpret_cast<uint32_t*>(&h0);
            H.y = *reinterpret_cast<uint32_t*>(&h1);
            *reinterpret_cast<uint2*>(oh + d) = H;
        }
        return;
    }
    id -= NB_RMS;
    {
        // zero 4096 floats per block (256 threads x 4 float4)
        const float4 z = make_float4(0.f, 0.f, 0.f, 0.f);
        size_t base = (size_t)id * 4096 + t * 4;
        #pragma unroll
        for (int j = 0; j < 4; j++) {
            size_t off = base + (size_t)j * 1024;
            if (off + 3 < (size_t)out_size)
                *reinterpret_cast<float4*>(out + off) = z;
            else {
                for (int e = 0; e < 4; e++)
                    if (off + e < (size_t)out_size) out[off + e] = 0.f;
            }
        }
    }
}

// ---------------------------------------------------------------------------
// GEMM1 (mma.sync f16, fp32 accum): H1[k] = tanh(An @ W0T^T + b0)
//   Block 128x128, K-step 32 (12 iters), 4-stage cp.async, ONE sync/iter.
//   8 warps as 4(M)x2(N): warp tile 32x64. Stage 16KB x4 = 64KB. 2 CTAs/SM.
//   [R9/R12 best config — 98.5% of this die's mma.sync ceiling]
// ---------------------------------------------------------------------------
#define G1_STAGE 16384
#define G1_SMEM  (4*G1_STAGE)

__global__ __launch_bounds__(256, 2) void gemm1_mma(const float* __restrict__ b0)
{
    extern __shared__ char smem[];
    const uint32_t sb = smem_u32(smem);
    const int t = threadIdx.x, wid = t >> 5, lane = t & 31;
    const int k = blockIdx.z, mb = blockIdx.y * 128, nb = blockIdx.x * 128;
    const int wm = wid & 3, wn = wid >> 2;

    const __half* gA = g_An  + ((size_t)k * MM  + mb) * DD;
    const __half* gB = g_W0T + ((size_t)k * DFF + nb) * DD;

    const __half* gbase[4];
    uint32_t sdst[4];
    #pragma unroll
    for (int j = 0; j < 4; j++) {
        int id = t + j * 256;
        int c = id & 3, r = (id >> 2) & 127;
        if (id < 512) { gbase[j] = gA + (size_t)r * DD + c * 8; sdst[j] = tswz(r, c); }
        else          { gbase[j] = gB + (size_t)r * DD + c * 8; sdst[j] = 8192u + tswz(r, c); }
    }

    const uint32_t laneXor = (uint32_t)((lane >> 4) << 4);
    uint32_t aO[2], bO[4];
    #pragma unroll
    for (int mf = 0; mf < 2; mf++)
        aO[mf] = tswz(wm * 32 + mf * 16 + (lane & 15), 0) ^ laneXor;
    #pragma unroll
    for (int g = 0; g < 4; g++)
        bO[g] = (tswz(wn * 64 + g * 16 + (lane & 15), 0) ^ laneXor) + 8192;

    float acc[2][8][4];
    #pragma unroll
    for (int a = 0; a < 2; a++)
        #pragma unroll
        for (int b = 0; b < 8; b++)
            #pragma unroll
            for (int c = 0; c < 4; c++) acc[a][b][c] = 0.f;

    #pragma unroll
    for (int st = 0; st < 3; st++) {
        #pragma unroll
        for (int j = 0; j < 4; j++)
            CP16(sb + st * G1_STAGE + sdst[j], gbase[j] + st * 32);
        CP_COMMIT();
    }

    #pragma unroll 1
    for (int it4 = 0; it4 < 3; ++it4) {
        #pragma unroll
        for (int ph = 0; ph < 4; ph++) {
            const int it = it4 * 4 + ph;
            const uint32_t stb = sb + (uint32_t)(ph * G1_STAGE);
            if (it < 10) CP_WAITN(2);
            else if (it == 10) CP_WAITN(1);
            else CP_WAITN(0);
            __syncthreads();
            if (it + 3 < 12) {
                const uint32_t stn = sb + (uint32_t)(((ph + 3) & 3) * G1_STAGE);
                const int k0 = (it + 3) * 32;
                #pragma unroll
                for (int j = 0; j < 4; j++) CP16(stn + sdst[j], gbase[j] + k0);
                CP_COMMIT();
            }

            #pragma unroll
            for (int kc = 0; kc < 2; kc++) {
                const uint32_t kx = (uint32_t)(kc << 5);
                uint32_t a[2][4], b[4][4];
                #pragma unroll
                for (int g = 0; g < 4; g++) ldsm4(b[g], stb + (bO[g] ^ kx));
                #pragma unroll
                for (int mf = 0; mf < 2; mf++) ldsm4(a[mf], stb + (aO[mf] ^ kx));
                #pragma unroll
                for (int mf = 0; mf < 2; mf++)
                    #pragma unroll
                    for (int nf = 0; nf < 8; nf++) {
                        int g = nf >> 1, s = nf & 1;
                        mma_f16(acc[mf][nf], a[mf], b[g][s], b[g][s + 2]);
                    }
            }
        }
    }

    // epilogue: bias + tanh -> g_H1 (fp16)
    #pragma unroll
    for (int nf = 0; nf < 8; nf++) {
        int n = nb + wn * 64 + nf * 8 + 2 * (lane & 3);
        float2 bias = *reinterpret_cast<const float2*>(&b0[k * DFF + n]);
        #pragma unroll
        for (int mf = 0; mf < 2; mf++) {
            #pragma unroll
            for (int h = 0; h < 2; h++) {
                int m = mb + wm * 32 + mf * 16 + (lane >> 2) + h * 8;
                float v0 = tanhf(acc[mf][nf][h * 2 + 0] + bias.x);
                float v1 = tanhf(acc[mf][nf][h * 2 + 1] + bias.y);
                __half2 hv = __floats2half2_rn(v0, v1);
                size_t off = ((size_t)k * MM + m) * DFF + n;
                *reinterpret_cast<uint32_t*>(g_H1 + off) =
                    *reinterpret_cast<uint32_t*>(&hv);
            }
        }
    }
}

// ---------------------------------------------------------------------------
// GEMM2 (mma.sync f16, fp32 accum): C = H1 @ W1T^T + b1; GLU; scatter-add.
//   Block 128x96, K-step 32 (48 iters), 4-stage cp.async, ONE sync/iter.
//   8 warps as 4(M)x2(N): warp tile 32x48. 2 CTAs/SM. (R9 best config.)
// ---------------------------------------------------------------------------
#define G2_STAGE 14336
#define G2_SMEM  (4*G2_STAGE)

__global__ __launch_bounds__(256, 2) void gemm2_mma(
    const float* __restrict__ b1, float* __restrict__ out)
{
    extern __shared__ char smem[];
    const uint32_t sb = smem_u32(smem);
    const int t = threadIdx.x, wid = t >> 5, lane = t & 31;
    const int k = blockIdx.y, mb = blockIdx.x * 128;
    const int wm = wid & 3, wn = wid >> 2;

    const __half* gA = g_H1  + ((size_t)k * MM + mb) * DFF;
    const __half* gB = g_W1T + (size_t)k * NOUT * DFF;

    const __half* gbase[4];
    uint32_t sdst[4];
    #pragma unroll
    for (int j = 0; j < 4; j++) {
        int id = t + j * 256;
        if (id >= 896) { gbase[j] = nullptr; sdst[j] = 0; continue; }
        int c = id & 3;
        if (id < 512) { int r = id >> 2;
                        gbase[j] = gA + (size_t)r * DFF + c * 8;
                        sdst[j]  = tswz(r, c); }
        else          { int r = (id - 512) >> 2;
                        gbase[j] = gB + (size_t)r * DFF + c * 8;
                        sdst[j]  = 8192u + tswz(r, c); }
    }

    const uint32_t laneXor = (uint32_t)((lane >> 4) << 4);
    uint32_t aO[2], bO[3];
    #pragma unroll
    for (int mf = 0; mf < 2; mf++)
        aO[mf] = tswz(wm * 32 + mf * 16 + (lane & 15), 0) ^ laneXor;
    #pragma unroll
    for (int g = 0; g < 3; g++)
        bO[g] = (tswz(wn * 48 + g * 16 + (lane & 15), 0) ^ laneXor) + 8192u;

    float acc[2][6][4];
    #pragma unroll
    for (int a = 0; a < 2; a++)
        #pragma unroll
        for (int b = 0; b < 6; b++)
            #pragma unroll
            for (int c = 0; c < 4; c++) acc[a][b][c] = 0.f;

    #pragma unroll
    for (int st = 0; st < 3; st++) {
        #pragma unroll
        for (int j = 0; j < 4; j++)
            if (gbase[j]) CP16(sb + st * G2_STAGE + sdst[j], gbase[j] + st * 32);
        CP_COMMIT();
    }

    #pragma unroll 1
    for (int it4 = 0; it4 < 12; ++it4) {
        #pragma unroll
        for (int ph = 0; ph < 4; ph++) {
            const int it = it4 * 4 + ph;
            const uint32_t stb = sb + (uint32_t)(ph * G2_STAGE);
            if (it < 46) CP_WAITN(2);
            else if (it == 46) CP_WAITN(1);
            else CP_WAITN(0);
            __syncthreads();
            if (it + 3 < 48) {
                const uint32_t stn = sb + (uint32_t)(((ph + 3) & 3) * G2_STAGE);
                const int k0 = (it + 3) * 32;
                #pragma unroll
                for (int j = 0; j < 4; j++)
                    if (gbase[j]) CP16(stn + sdst[j], gbase[j] + k0);
                CP_COMMIT();
            }

            #pragma unroll
            for (int kc = 0; kc < 2; kc++) {
                const uint32_t kx = (uint32_t)(kc << 5);
                uint32_t a[2][4], b[3][4];
                #pragma unroll
                for (int g = 0; g < 3; g++) ldsm4(b[g], stb + (bO[g] ^ kx));
                #pragma unroll
                for (int mf = 0; mf < 2; mf++) ldsm4(a[mf], stb + (aO[mf] ^ kx));
                #pragma unroll
                for (int mf = 0; mf < 2; mf++)
                    #pragma unroll
                    for (int nf = 0; nf < 6; nf++) {
                        int g = nf >> 1, s = nf & 1;
                        mma_f16(acc[mf][nf], a[mf], b[g][s], b[g][s + 2]);
                    }
            }
        }
    }
    __syncthreads();

    // epilogue: stage C in smem, then GLU + scatter-add
    float* Cs = reinterpret_cast<float*>(smem);   // 128 x 100 floats
    #pragma unroll
    for (int nf = 0; nf < 6; nf++) {
        int n = wn * 48 + nf * 8 + 2 * (lane & 3);
        #pragma unroll
        for (int mf = 0; mf < 2; mf++) {
            #pragma unroll
            for (int h = 0; h < 2; h++) {
                int m = wm * 32 + mf * 16 + (lane >> 2) + h * 8;
                float2 v;
                v.x = acc[mf][nf][h * 2 + 0];
                v.y = acc[mf][nf][h * 2 + 1];
                *reinterpret_cast<float2*>(&Cs[m * 100 + n]) = v;
            }
        }
    }
    __syncthreads();

    {
        int m = t >> 1;
        int j0 = (t & 1) * 24;
        int gm = mb + m, bidx = gm >> 9, tidx = gm & 511;
        const float* bA = b1 + k * NOUT;
        #pragma unroll
        for (int jj = 0; jj < 24; jj++) {
            int j = j0 + jj;
            float a = Cs[m * 100 + j]      + bA[j];
            float g = Cs[m * 100 + j + 48] + bA[j + 48];
            float ch = a * (1.0f / (1.0f + __expf(-g)));
            int p = k * 32 + j;
            int oi = ((bidx * 2 + (p & 1)) * TT + tidx) * FREQ + (p >> 1);
            atomicAdd(&out[oi], ch);
        }
    }
}

// ---------------------------------------------------------------------------
extern "C" void kernel_launch(void* const* d_in, const int* in_sizes, int n_in,
                              void* d_out, int out_size)
{
    (void)in_sizes; (void)n_in;
    const float* x     = (const float*)d_in[0];
    const float* gamma = (const float*)d_in[1];
    const float* W0    = (const float*)d_in[2];
    const float* b0    = (const float*)d_in[3];
    const float* W1    = (const float*)d_in[4];
    const float* b1    = (const float*)d_in[5];
    float*       out   = (float*)d_out;

    cudaFuncSetAttribute(gemm1_mma, cudaFuncAttributeMaxDynamicSharedMemorySize, G1_SMEM);
    cudaFuncSetAttribute(gemm2_mma, cudaFuncAttributeMaxDynamicSharedMemorySize, G2_SMEM);

    // single fused preprocessing launch (transposes + rms + output zeroing)
    pre_fused<<<NB_W0 + NB_W1 + NB_RMS + NB_ZERO, 256>>>(
        x, gamma, W0, W1, out, out_size);

    dim3 g1(DFF / 128, MM / 128, KK);      // (12, 16, 63)
    gemm1_mma<<<g1, 256, G1_SMEM>>>(b0);

    dim3 g2(MM / 128, KK);                 // (16, 63)
    gemm2_mma<<<g2, 256, G2_SMEM>>>(b1, out);
}